// round 2
// baseline (speedup 1.0000x reference)
#include <cuda_runtime.h>
#include <math.h>

#define NN 50000
#define TT 1000
#define KL 5
#define KR 15
#define NC 5
#define TWOPI 6.28318530717958647692f
#define NCHUNK 64

// cluster accumulators: per cluster 13 floats: [count, sumAmp*4, sumCos*4, sumSin*4]
__device__ float g_cluster[NC * 13];
// per-node cos/sin of the 4 seasonal phases, packed 32B per node
__device__ float4 g_cs[NN * 2];
// per-node coefficients: {c0, lt, a0, a1} {a2, a3, b0, b1} {b2, b3, 0, 0}
__device__ float4 g_coef[NN * 3];

__global__ void k_zero() {
    if (threadIdx.x < NC * 13) g_cluster[threadIdx.x] = 0.f;
}

__global__ void k_pre(const float* __restrict__ amp, const float* __restrict__ ph,
                      const int* __restrict__ lab) {
    __shared__ float s_acc[NC * 13];
    for (int i = threadIdx.x; i < NC * 13; i += blockDim.x) s_acc[i] = 0.f;
    __syncthreads();
    int stride = gridDim.x * blockDim.x;
    for (int n = blockIdx.x * blockDim.x + threadIdx.x; n < NN; n += stride) {
        float4 p = reinterpret_cast<const float4*>(ph)[n];
        float4 cs, sn;
        sincosf(p.x, &sn.x, &cs.x);
        sincosf(p.y, &sn.y, &cs.y);
        sincosf(p.z, &sn.z, &cs.z);
        sincosf(p.w, &sn.w, &cs.w);
        g_cs[n * 2 + 0] = cs;
        g_cs[n * 2 + 1] = sn;
        float4 a = reinterpret_cast<const float4*>(amp)[n];
        int c = lab[n];
        float* acc = s_acc + c * 13;
        atomicAdd(acc + 0, 1.f);
        atomicAdd(acc + 1, a.x);  atomicAdd(acc + 2, a.y);
        atomicAdd(acc + 3, a.z);  atomicAdd(acc + 4, a.w);
        atomicAdd(acc + 5, cs.x); atomicAdd(acc + 6, cs.y);
        atomicAdd(acc + 7, cs.z); atomicAdd(acc + 8, cs.w);
        atomicAdd(acc + 9, sn.x); atomicAdd(acc + 10, sn.y);
        atomicAdd(acc + 11, sn.z); atomicAdd(acc + 12, sn.w);
    }
    __syncthreads();
    for (int i = threadIdx.x; i < NC * 13; i += blockDim.x)
        atomicAdd(&g_cluster[i], s_acc[i]);
}

__global__ void k_coef(const float* __restrict__ amp, const float* __restrict__ ph,
                       const float* __restrict__ lw, const float* __restrict__ rw,
                       const int* __restrict__ li, const int* __restrict__ ri,
                       const int* __restrict__ lab,
                       const float* __restrict__ co, const float* __restrict__ lt) {
    int n = blockIdx.x * blockDim.x + threadIdx.x;
    if (n >= NN) return;
    float4 a4 = reinterpret_cast<const float4*>(amp)[n];
    float4 p4 = reinterpret_cast<const float4*>(ph)[n];

    float la[4] = {0,0,0,0}, lc[4] = {0,0,0,0}, ls[4] = {0,0,0,0};
    float ra[4] = {0,0,0,0}, rc[4] = {0,0,0,0}, rs[4] = {0,0,0,0};

    #pragma unroll
    for (int k = 0; k < KL; k++) {
        int j = li[n * KL + k];
        float w = lw[n * KL + k];
        float4 aj = reinterpret_cast<const float4*>(amp)[j];
        float4 cj = g_cs[j * 2 + 0];
        float4 sj = g_cs[j * 2 + 1];
        la[0] = fmaf(aj.x, w, la[0]); la[1] = fmaf(aj.y, w, la[1]);
        la[2] = fmaf(aj.z, w, la[2]); la[3] = fmaf(aj.w, w, la[3]);
        lc[0] = fmaf(cj.x, w, lc[0]); lc[1] = fmaf(cj.y, w, lc[1]);
        lc[2] = fmaf(cj.z, w, lc[2]); lc[3] = fmaf(cj.w, w, lc[3]);
        ls[0] = fmaf(sj.x, w, ls[0]); ls[1] = fmaf(sj.y, w, ls[1]);
        ls[2] = fmaf(sj.z, w, ls[2]); ls[3] = fmaf(sj.w, w, ls[3]);
    }
    #pragma unroll
    for (int k = 0; k < KR; k++) {
        int j = ri[n * KR + k];
        float w = rw[n * KR + k];
        float4 aj = reinterpret_cast<const float4*>(amp)[j];
        float4 cj = g_cs[j * 2 + 0];
        float4 sj = g_cs[j * 2 + 1];
        ra[0] = fmaf(aj.x, w, ra[0]); ra[1] = fmaf(aj.y, w, ra[1]);
        ra[2] = fmaf(aj.z, w, ra[2]); ra[3] = fmaf(aj.w, w, ra[3]);
        rc[0] = fmaf(cj.x, w, rc[0]); rc[1] = fmaf(cj.y, w, rc[1]);
        rc[2] = fmaf(cj.z, w, rc[2]); rc[3] = fmaf(cj.w, w, rc[3]);
        rs[0] = fmaf(sj.x, w, rs[0]); rs[1] = fmaf(sj.y, w, rs[1]);
        rs[2] = fmaf(sj.z, w, rs[2]); rs[3] = fmaf(sj.w, w, rs[3]);
    }

    int c = lab[n];
    float cnt = g_cluster[c * 13];
    bool big = cnt > 1.0f;
    float inv = 1.f / fmaxf(cnt, 1.f);
    float aP[4] = {a4.x, a4.y, a4.z, a4.w};
    float pP[4] = {p4.x, p4.y, p4.z, p4.w};
    float av[4], bv[4];
    #pragma unroll
    for (int i = 0; i < 4; i++) {
        float campU = big ? g_cluster[c * 13 + 1 + i] * inv : aP[i];
        // combined = 0.5*local + 0.3*(0.7*regional_sum) + 0.2*cluster
        float ampO = 0.7f * aP[i] + 0.3f * (0.5f * la[i] + 0.21f * ra[i] + 0.2f * campU);
        float cphU = big ? atan2f(g_cluster[c * 13 + 9 + i], g_cluster[c * 13 + 5 + i]) : pP[i];
        float phL = atan2f(ls[i], lc[i]);
        float phR = atan2f(rs[i], rc[i]);
        float phO = 0.7f * pP[i] + 0.3f * (0.5f * phL + 0.3f * phR + 0.2f * cphU);
        float s, cc;
        sincosf(phO, &s, &cc);
        av[i] = ampO * cc;   // coefficient for sin(w t)
        bv[i] = ampO * s;    // coefficient for cos(w t)
    }
    g_coef[n * 3 + 0] = make_float4(co[n], lt[n], av[0], av[1]);
    g_coef[n * 3 + 1] = make_float4(av[2], av[3], bv[0], bv[1]);
    g_coef[n * 3 + 2] = make_float4(bv[2], bv[3], 0.f, 0.f);
}

// out[n,t] = c0 + lt*t + sum_i a_i*sin(w_i t) + b_i*cos(w_i t)
#define EVAL(st, S, C) \
    fmaf(D.y, (C)[3], fmaf(D.x, (C)[2], fmaf(B.w, (C)[1], fmaf(B.z, (C)[0], \
    fmaf(B.y, (S)[3], fmaf(B.x, (S)[2], fmaf(A.w, (S)[1], fmaf(A.z, (S)[0], \
    fmaf(A.y, (st), A.x)))))))))

__global__ __launch_bounds__(256) void k_fill(const float* __restrict__ tv,
                                              float* __restrict__ out) {
    __shared__ float4 s_coef[NCHUNK * 3];
    int base = blockIdx.x * NCHUNK;
    int nn = min(NCHUNK, NN - base);
    for (int i = threadIdx.x; i < nn * 3; i += blockDim.x)
        s_coef[i] = g_coef[base * 3 + i];
    __syncthreads();

    int t0 = threadIdx.x * 4;
    if (t0 >= TT) return;  // threads 250..255 only help staging (TT=1000)

    float st0 = tv[t0], st1 = tv[t0 + 1], st2 = tv[t0 + 2], st3 = tv[t0 + 3];
    float S0[4], C0[4], S1[4], C1[4], S2[4], C2[4], S3[4], C3[4];
    const float w[4] = {TWOPI * 4.f, TWOPI * 2.f, TWOPI, TWOPI * 0.5f};
    #pragma unroll
    for (int i = 0; i < 4; i++) {
        sincosf(w[i] * st0, &S0[i], &C0[i]);
        sincosf(w[i] * st1, &S1[i], &C1[i]);
        sincosf(w[i] * st2, &S2[i], &C2[i]);
        sincosf(w[i] * st3, &S3[i], &C3[i]);
    }

    #pragma unroll 2
    for (int j = 0; j < nn; j++) {
        float4 A = s_coef[j * 3 + 0];
        float4 B = s_coef[j * 3 + 1];
        float4 D = s_coef[j * 3 + 2];
        float4 o;
        o.x = EVAL(st0, S0, C0);
        o.y = EVAL(st1, S1, C1);
        o.z = EVAL(st2, S2, C2);
        o.w = EVAL(st3, S3, C3);
        reinterpret_cast<float4*>(out + (size_t)(base + j) * TT + t0)[0] = o;
    }
}

extern "C" void kernel_launch(void* const* d_in, const int* in_sizes, int n_in,
                              void* d_out, int out_size) {
    const float* tv  = (const float*)d_in[0];  // time_vector        [1000]
    const float* co  = (const float*)d_in[1];  // constant_offset    [50000]
    const float* lt  = (const float*)d_in[2];  // linear_trend       [50000]
    const float* amp = (const float*)d_in[3];  // seasonal_amplitudes[50000,4]
    const float* ph  = (const float*)d_in[4];  // seasonal_phases    [50000,4]
    const float* lw  = (const float*)d_in[5];  // local_w            [50000,5]
    const float* rw  = (const float*)d_in[6];  // regional_w         [50000,15]
    const int*   li  = (const int*)d_in[7];    // local_idx          [50000,5]
    const int*   ri  = (const int*)d_in[8];    // regional_idx       [50000,15]
    const int*   lab = (const int*)d_in[9];    // cluster_labels     [50000]
    float* out = (float*)d_out;

    k_zero<<<1, 128>>>();
    k_pre<<<196, 256>>>(amp, ph, lab);
    k_coef<<<196, 256>>>(amp, ph, lw, rw, li, ri, lab, co, lt);
    k_fill<<<(NN + NCHUNK - 1) / NCHUNK, 256>>>(tv, out);
}

// round 3
// speedup vs baseline: 1.0562x; 1.0562x over previous
#include <cuda_runtime.h>
#include <math.h>

#define NN 50000
#define TT 1000
#define KL 5
#define KR 15
#define NC 5
#define TWOPI 6.28318530717958647692f
#define NCHUNK 64
#define PREBLK 98
#define PRETHR 512

typedef unsigned long long ull;

__device__ __forceinline__ ull pk2(float lo, float hi) {
    ull r; asm("mov.b64 %0,{%1,%2};" : "=l"(r) : "f"(lo), "f"(hi)); return r;
}
__device__ __forceinline__ float2 upk2(ull v) {
    float2 f; asm("mov.b64 {%0,%1},%2;" : "=f"(f.x), "=f"(f.y) : "l"(v)); return f;
}
__device__ __forceinline__ ull ffma2(ull a, ull b, ull c) {
    ull d; asm("fma.rn.f32x2 %0,%1,%2,%3;" : "=l"(d) : "l"(a), "l"(b), "l"(c)); return d;
}

// per-node cos/sin of the 4 seasonal phases (float4 cos, float4 sin)
__device__ float4 g_cs[NN * 2];
// per-block partial cluster sums: [count, sumAmp*4, sumCos*4, sumSin*4] per cluster
__device__ float g_partial[PREBLK * 65];
// per-node coefficients, order [c0, lt, a0, a1, a2, a3, b0, b1, b2, b3, 0, 0]
__device__ float g_coefs[NN * 12];

// ---------------------------------------------------------------------------
// Stage 1: per-node sincos of phases + per-block partial cluster sums.
// Per-warp shared banks to cut shared-atomic conflict degree ~8x.
// ---------------------------------------------------------------------------
__global__ __launch_bounds__(PRETHR) void k_pre(const float4* __restrict__ amp,
                                                const float4* __restrict__ ph,
                                                const int* __restrict__ lab) {
    __shared__ float s_acc[16 * 65];
    int tid = threadIdx.x;
    for (int i = tid; i < 16 * 65; i += PRETHR) s_acc[i] = 0.f;
    __syncthreads();

    int n = blockIdx.x * PRETHR + tid;
    if (n < NN) {
        float4 p = ph[n];
        float4 cs, sn;
        __sincosf(p.x, &sn.x, &cs.x);
        __sincosf(p.y, &sn.y, &cs.y);
        __sincosf(p.z, &sn.z, &cs.z);
        __sincosf(p.w, &sn.w, &cs.w);
        g_cs[n * 2 + 0] = cs;
        g_cs[n * 2 + 1] = sn;
        float4 a = amp[n];
        int c = lab[n];
        float* acc = s_acc + (tid >> 5) * 65 + c * 13;
        atomicAdd(acc + 0, 1.f);
        atomicAdd(acc + 1, a.x);  atomicAdd(acc + 2, a.y);
        atomicAdd(acc + 3, a.z);  atomicAdd(acc + 4, a.w);
        atomicAdd(acc + 5, cs.x); atomicAdd(acc + 6, cs.y);
        atomicAdd(acc + 7, cs.z); atomicAdd(acc + 8, cs.w);
        atomicAdd(acc + 9, sn.x); atomicAdd(acc + 10, sn.y);
        atomicAdd(acc + 11, sn.z); atomicAdd(acc + 12, sn.w);
    }
    __syncthreads();
    for (int i = tid; i < 65; i += PRETHR) {
        float s = 0.f;
        #pragma unroll
        for (int w = 0; w < 16; w++) s += s_acc[w * 65 + i];
        g_partial[blockIdx.x * 65 + i] = s;
    }
}

// ---------------------------------------------------------------------------
// Stage 2: reduce cluster partials (per block, in shared), precompute cluster
// circular means once, then per-node message passing -> harmonic coefficients.
// Gathers use free f32x2 packing (float4 == 2x b64 operands).
// ---------------------------------------------------------------------------
__global__ __launch_bounds__(256) void k_coef(const float* __restrict__ amp,
                                              const float* __restrict__ ph,
                                              const float* __restrict__ lw,
                                              const float* __restrict__ rw,
                                              const int* __restrict__ li,
                                              const int* __restrict__ ri,
                                              const int* __restrict__ lab,
                                              const float* __restrict__ co,
                                              const float* __restrict__ lt) {
    __shared__ float s_cl[65];
    __shared__ float s_mA[NC * 4];   // cluster mean amplitude
    __shared__ float s_cPh[NC * 4];  // cluster circular mean phase
    __shared__ int   s_big[NC];
    int tid = threadIdx.x;

    if (tid < 65) {
        float s = 0.f;
        for (int r = 0; r < PREBLK; r++) s += g_partial[r * 65 + tid];
        s_cl[tid] = s;
    }
    __syncthreads();
    if (tid < NC * 4) {
        int c = tid >> 2, i = tid & 3;
        float cnt = s_cl[c * 13];
        if (i == 0) s_big[c] = (cnt > 1.0f);
        s_mA[tid]  = s_cl[c * 13 + 1 + i] / fmaxf(cnt, 1.f);
        s_cPh[tid] = atan2f(s_cl[c * 13 + 9 + i], s_cl[c * 13 + 5 + i]);
    }
    __syncthreads();

    int n = blockIdx.x * 256 + tid;
    if (n >= NN) return;

    const ulonglong2* ampP = (const ulonglong2*)amp;
    const ulonglong2* csP  = (const ulonglong2*)g_cs;

    float4 a4 = ((const float4*)amp)[n];
    float4 p4 = ((const float4*)ph)[n];

    ull la01 = 0, la23 = 0, lc01 = 0, lc23 = 0, ls01 = 0, ls23 = 0;
    ull ra01 = 0, ra23 = 0, rc01 = 0, rc23 = 0, rs01 = 0, rs23 = 0;

    #pragma unroll
    for (int k = 0; k < KL; k++) {
        int j = li[n * KL + k];
        ull wP = pk2(lw[n * KL + k], lw[n * KL + k]);
        ulonglong2 aj = ampP[j];
        ulonglong2 cj = csP[j * 2 + 0];
        ulonglong2 sj = csP[j * 2 + 1];
        la01 = ffma2(aj.x, wP, la01); la23 = ffma2(aj.y, wP, la23);
        lc01 = ffma2(cj.x, wP, lc01); lc23 = ffma2(cj.y, wP, lc23);
        ls01 = ffma2(sj.x, wP, ls01); ls23 = ffma2(sj.y, wP, ls23);
    }
    #pragma unroll
    for (int k = 0; k < KR; k++) {
        int j = ri[n * KR + k];
        ull wP = pk2(rw[n * KR + k], rw[n * KR + k]);
        ulonglong2 aj = ampP[j];
        ulonglong2 cj = csP[j * 2 + 0];
        ulonglong2 sj = csP[j * 2 + 1];
        ra01 = ffma2(aj.x, wP, ra01); ra23 = ffma2(aj.y, wP, ra23);
        rc01 = ffma2(cj.x, wP, rc01); rc23 = ffma2(cj.y, wP, rc23);
        rs01 = ffma2(sj.x, wP, rs01); rs23 = ffma2(sj.y, wP, rs23);
    }

    float2 t;
    float la[4], lc[4], ls[4], ra[4], rc[4], rs[4];
    t = upk2(la01); la[0] = t.x; la[1] = t.y;  t = upk2(la23); la[2] = t.x; la[3] = t.y;
    t = upk2(lc01); lc[0] = t.x; lc[1] = t.y;  t = upk2(lc23); lc[2] = t.x; lc[3] = t.y;
    t = upk2(ls01); ls[0] = t.x; ls[1] = t.y;  t = upk2(ls23); ls[2] = t.x; ls[3] = t.y;
    t = upk2(ra01); ra[0] = t.x; ra[1] = t.y;  t = upk2(ra23); ra[2] = t.x; ra[3] = t.y;
    t = upk2(rc01); rc[0] = t.x; rc[1] = t.y;  t = upk2(rc23); rc[2] = t.x; rc[3] = t.y;
    t = upk2(rs01); rs[0] = t.x; rs[1] = t.y;  t = upk2(rs23); rs[2] = t.x; rs[3] = t.y;

    int c = lab[n];
    bool big = s_big[c];
    float aP[4] = {a4.x, a4.y, a4.z, a4.w};
    float pP[4] = {p4.x, p4.y, p4.z, p4.w};
    float outv[12];
    outv[0] = co[n];
    outv[1] = lt[n];
    #pragma unroll
    for (int i = 0; i < 4; i++) {
        float campU = big ? s_mA[c * 4 + i] : aP[i];
        // combined = 0.5*local + 0.3*(0.7*regional_sum) + 0.2*cluster
        float ampO = 0.7f * aP[i] + 0.3f * (0.5f * la[i] + 0.21f * ra[i] + 0.2f * campU);
        float cphU = big ? s_cPh[c * 4 + i] : pP[i];
        float phL = atan2f(ls[i], lc[i]);
        float phR = atan2f(rs[i], rc[i]);
        float phO = 0.7f * pP[i] + 0.3f * (0.5f * phL + 0.3f * phR + 0.2f * cphU);
        float s, cc;
        __sincosf(phO, &s, &cc);
        outv[2 + i] = ampO * cc;  // coeff of sin(w t)
        outv[6 + i] = ampO * s;   // coeff of cos(w t)
    }
    outv[10] = 0.f; outv[11] = 0.f;
    float4* dst = (float4*)(g_coefs + n * 12);
    dst[0] = make_float4(outv[0], outv[1], outv[2], outv[3]);
    dst[1] = make_float4(outv[4], outv[5], outv[6], outv[7]);
    dst[2] = make_float4(outv[8], outv[9], outv[10], outv[11]);
}

// ---------------------------------------------------------------------------
// Stage 3: 200MB fill.  out[n,t] = c0 + lt*t + sum_i a_i*sin(w_i t)+b_i*cos(w_i t)
// Coefficients staged PRE-DUPLICATED as packed f32x2 in shared; inner loop is
// 18 fma.rn.f32x2 + 5 broadcast LDS.128 + 1 STG.128 per node.
// ---------------------------------------------------------------------------
__global__ __launch_bounds__(256) void k_fill(const float* __restrict__ tv,
                                              float* __restrict__ out) {
    __shared__ ulonglong2 s_cp[NCHUNK * 5];  // per node: (c0,lt)(a0,a1)(a2,a3)(b0,b1)(b2,b3), each dup-packed
    int base = blockIdx.x * NCHUNK;
    int nn = min(NCHUNK, NN - base);
    {
        ull* s_raw = (ull*)s_cp;
        for (int i = threadIdx.x; i < nn * 10; i += 256) {
            int node = i / 10, s = i - node * 10;
            float v = g_coefs[(base + node) * 12 + s];
            s_raw[node * 10 + s] = pk2(v, v);
        }
    }
    __syncthreads();

    int t0 = threadIdx.x * 4;
    if (t0 >= TT) return;  // threads 250..255 only helped staging

    float4 tvv = ((const float4*)tv)[threadIdx.x];
    ull T01 = pk2(tvv.x, tvv.y);
    ull T23 = pk2(tvv.z, tvv.w);

    const float w[4] = {TWOPI * 4.f, TWOPI * 2.f, TWOPI, TWOPI * 0.5f};
    ull S01[4], C01[4], S23[4], C23[4];
    #pragma unroll
    for (int i = 0; i < 4; i++) {
        float s0, c0, s1, c1, s2, c2, s3, c3;
        sincosf(w[i] * tvv.x, &s0, &c0);
        sincosf(w[i] * tvv.y, &s1, &c1);
        sincosf(w[i] * tvv.z, &s2, &c2);
        sincosf(w[i] * tvv.w, &s3, &c3);
        S01[i] = pk2(s0, s1); C01[i] = pk2(c0, c1);
        S23[i] = pk2(s2, s3); C23[i] = pk2(c2, c3);
    }

    #pragma unroll 2
    for (int j = 0; j < nn; j++) {
        ulonglong2 e0 = s_cp[j * 5 + 0];
        ulonglong2 e1 = s_cp[j * 5 + 1];
        ulonglong2 e2 = s_cp[j * 5 + 2];
        ulonglong2 e3 = s_cp[j * 5 + 3];
        ulonglong2 e4 = s_cp[j * 5 + 4];
        ull r0 = ffma2(e0.y, T01, e0.x);
        r0 = ffma2(e1.x, S01[0], r0); r0 = ffma2(e1.y, S01[1], r0);
        r0 = ffma2(e2.x, S01[2], r0); r0 = ffma2(e2.y, S01[3], r0);
        r0 = ffma2(e3.x, C01[0], r0); r0 = ffma2(e3.y, C01[1], r0);
        r0 = ffma2(e4.x, C01[2], r0); r0 = ffma2(e4.y, C01[3], r0);
        ull r1 = ffma2(e0.y, T23, e0.x);
        r1 = ffma2(e1.x, S23[0], r1); r1 = ffma2(e1.y, S23[1], r1);
        r1 = ffma2(e2.x, S23[2], r1); r1 = ffma2(e2.y, S23[3], r1);
        r1 = ffma2(e3.x, C23[0], r1); r1 = ffma2(e3.y, C23[1], r1);
        r1 = ffma2(e4.x, C23[2], r1); r1 = ffma2(e4.y, C23[3], r1);
        ulonglong2 o; o.x = r0; o.y = r1;
        *reinterpret_cast<ulonglong2*>(out + (size_t)(base + j) * TT + t0) = o;
    }
}

extern "C" void kernel_launch(void* const* d_in, const int* in_sizes, int n_in,
                              void* d_out, int out_size) {
    const float* tv  = (const float*)d_in[0];  // time_vector        [1000]
    const float* co  = (const float*)d_in[1];  // constant_offset    [50000]
    const float* lt  = (const float*)d_in[2];  // linear_trend       [50000]
    const float* amp = (const float*)d_in[3];  // seasonal_amplitudes[50000,4]
    const float* ph  = (const float*)d_in[4];  // seasonal_phases    [50000,4]
    const float* lw  = (const float*)d_in[5];  // local_w            [50000,5]
    const float* rw  = (const float*)d_in[6];  // regional_w         [50000,15]
    const int*   li  = (const int*)d_in[7];    // local_idx          [50000,5]
    const int*   ri  = (const int*)d_in[8];    // regional_idx       [50000,15]
    const int*   lab = (const int*)d_in[9];    // cluster_labels     [50000]
    float* out = (float*)d_out;

    k_pre<<<PREBLK, PRETHR>>>((const float4*)amp, (const float4*)ph, lab);
    k_coef<<<(NN + 255) / 256, 256>>>(amp, ph, lw, rw, li, ri, lab, co, lt);
    k_fill<<<(NN + NCHUNK - 1) / NCHUNK, 256>>>(tv, out);
}

// round 4
// speedup vs baseline: 1.1342x; 1.0738x over previous
#include <cuda_runtime.h>
#include <math.h>

#define NN 50000
#define TT 1000
#define KL 5
#define KR 15
#define NC 5
#define TWOPI 6.28318530717958647692f
#define PREBLK 98
#define PRETHR 512
#define GRIDF 592
#define MAXSLAB 85

typedef unsigned long long ull;

__device__ __forceinline__ ull pk2(float lo, float hi) {
    ull r; asm("mov.b64 %0,{%1,%2};" : "=l"(r) : "f"(lo), "f"(hi)); return r;
}
__device__ __forceinline__ float2 upk2(ull v) {
    float2 f; asm("mov.b64 {%0,%1},%2;" : "=f"(f.x), "=f"(f.y) : "l"(v)); return f;
}
__device__ __forceinline__ ull ffma2(ull a, ull b, ull c) {
    ull d; asm("fma.rn.f32x2 %0,%1,%2,%3;" : "=l"(d) : "l"(a), "l"(b), "l"(c)); return d;
}

// per-node cos/sin of the 4 seasonal phases (float4 cos, float4 sin)
__device__ float4 g_cs[NN * 2];
// per-block partial cluster sums: [count, sumAmp*4, sumCos*4, sumSin*4] x NC
__device__ float g_partial[PREBLK * 65];
// per-node coefficients [c0, lt, a0..a3, b0..b3, 0, 0]
__device__ float g_coefs[NN * 12];

// ---------------------------------------------------------------------------
// Stage 1: per-node sincos of phases + per-block partial cluster sums.
// NO atomics: per-cluster warp butterfly reduction, then cross-warp fold in
// shared, plain store of the block partial. Deterministic.
// ---------------------------------------------------------------------------
__global__ __launch_bounds__(PRETHR) void k_pre(const float4* __restrict__ amp,
                                                const float4* __restrict__ ph,
                                                const int* __restrict__ lab) {
    __shared__ float s_part[16 * 65];
    int tid = threadIdx.x;
    int wid = tid >> 5, lane = tid & 31;
    int n = blockIdx.x * PRETHR + tid;

    float v[13];
    int c = -1;
    if (n < NN) {
        float4 p = ph[n];
        float4 cs, sn;
        __sincosf(p.x, &sn.x, &cs.x);
        __sincosf(p.y, &sn.y, &cs.y);
        __sincosf(p.z, &sn.z, &cs.z);
        __sincosf(p.w, &sn.w, &cs.w);
        g_cs[n * 2 + 0] = cs;
        g_cs[n * 2 + 1] = sn;
        float4 a = amp[n];
        c = lab[n];
        v[0] = 1.f;
        v[1] = a.x;  v[2] = a.y;  v[3] = a.z;  v[4] = a.w;
        v[5] = cs.x; v[6] = cs.y; v[7] = cs.z; v[8] = cs.w;
        v[9] = sn.x; v[10] = sn.y; v[11] = sn.z; v[12] = sn.w;
    } else {
        #pragma unroll
        for (int i = 0; i < 13; i++) v[i] = 0.f;
    }

    #pragma unroll
    for (int cc = 0; cc < NC; cc++) {
        #pragma unroll
        for (int i = 0; i < 13; i++) {
            float x = (c == cc) ? v[i] : 0.f;
            x += __shfl_xor_sync(0xffffffffu, x, 16);
            x += __shfl_xor_sync(0xffffffffu, x, 8);
            x += __shfl_xor_sync(0xffffffffu, x, 4);
            x += __shfl_xor_sync(0xffffffffu, x, 2);
            x += __shfl_xor_sync(0xffffffffu, x, 1);
            if (lane == 0) s_part[wid * 65 + cc * 13 + i] = x;
        }
    }
    __syncthreads();
    if (tid < 65) {
        float s = 0.f;
        #pragma unroll
        for (int w = 0; w < 16; w++) s += s_part[w * 65 + tid];
        g_partial[blockIdx.x * 65 + tid] = s;
    }
}

// ---------------------------------------------------------------------------
// Stage 2: reduce cluster partials (per block), precompute cluster circular
// means once per block, then per-node message passing -> harmonic coeffs.
// ---------------------------------------------------------------------------
__global__ __launch_bounds__(256) void k_coef(const float* __restrict__ amp,
                                              const float* __restrict__ ph,
                                              const float* __restrict__ lw,
                                              const float* __restrict__ rw,
                                              const int* __restrict__ li,
                                              const int* __restrict__ ri,
                                              const int* __restrict__ lab,
                                              const float* __restrict__ co,
                                              const float* __restrict__ lt) {
    __shared__ float s_cl[65];
    __shared__ float s_mA[NC * 4];
    __shared__ float s_cPh[NC * 4];
    __shared__ int   s_big[NC];
    int tid = threadIdx.x;

    if (tid < 65) {
        float s = 0.f;
        for (int r = 0; r < PREBLK; r++) s += g_partial[r * 65 + tid];
        s_cl[tid] = s;
    }
    __syncthreads();
    if (tid < NC * 4) {
        int c = tid >> 2, i = tid & 3;
        float cnt = s_cl[c * 13];
        if (i == 0) s_big[c] = (cnt > 1.0f);
        s_mA[tid]  = s_cl[c * 13 + 1 + i] / fmaxf(cnt, 1.f);
        s_cPh[tid] = atan2f(s_cl[c * 13 + 9 + i], s_cl[c * 13 + 5 + i]);
    }
    __syncthreads();

    int n = blockIdx.x * 256 + tid;
    if (n >= NN) return;

    const ulonglong2* ampP = (const ulonglong2*)amp;
    const ulonglong2* csP  = (const ulonglong2*)g_cs;

    float4 a4 = ((const float4*)amp)[n];
    float4 p4 = ((const float4*)ph)[n];

    ull la01 = 0, la23 = 0, lc01 = 0, lc23 = 0, ls01 = 0, ls23 = 0;
    ull ra01 = 0, ra23 = 0, rc01 = 0, rc23 = 0, rs01 = 0, rs23 = 0;

    #pragma unroll
    for (int k = 0; k < KL; k++) {
        int j = li[n * KL + k];
        float w = lw[n * KL + k];
        ull wP = pk2(w, w);
        ulonglong2 aj = ampP[j];
        ulonglong2 cj = csP[j * 2 + 0];
        ulonglong2 sj = csP[j * 2 + 1];
        la01 = ffma2(aj.x, wP, la01); la23 = ffma2(aj.y, wP, la23);
        lc01 = ffma2(cj.x, wP, lc01); lc23 = ffma2(cj.y, wP, lc23);
        ls01 = ffma2(sj.x, wP, ls01); ls23 = ffma2(sj.y, wP, ls23);
    }
    #pragma unroll
    for (int k = 0; k < KR; k++) {
        int j = ri[n * KR + k];
        float w = rw[n * KR + k];
        ull wP = pk2(w, w);
        ulonglong2 aj = ampP[j];
        ulonglong2 cj = csP[j * 2 + 0];
        ulonglong2 sj = csP[j * 2 + 1];
        ra01 = ffma2(aj.x, wP, ra01); ra23 = ffma2(aj.y, wP, ra23);
        rc01 = ffma2(cj.x, wP, rc01); rc23 = ffma2(cj.y, wP, rc23);
        rs01 = ffma2(sj.x, wP, rs01); rs23 = ffma2(sj.y, wP, rs23);
    }

    float2 t;
    float la[4], lc[4], ls[4], ra[4], rc[4], rs[4];
    t = upk2(la01); la[0] = t.x; la[1] = t.y;  t = upk2(la23); la[2] = t.x; la[3] = t.y;
    t = upk2(lc01); lc[0] = t.x; lc[1] = t.y;  t = upk2(lc23); lc[2] = t.x; lc[3] = t.y;
    t = upk2(ls01); ls[0] = t.x; ls[1] = t.y;  t = upk2(ls23); ls[2] = t.x; ls[3] = t.y;
    t = upk2(ra01); ra[0] = t.x; ra[1] = t.y;  t = upk2(ra23); ra[2] = t.x; ra[3] = t.y;
    t = upk2(rc01); rc[0] = t.x; rc[1] = t.y;  t = upk2(rc23); rc[2] = t.x; rc[3] = t.y;
    t = upk2(rs01); rs[0] = t.x; rs[1] = t.y;  t = upk2(rs23); rs[2] = t.x; rs[3] = t.y;

    int c = lab[n];
    bool big = s_big[c];
    float aP[4] = {a4.x, a4.y, a4.z, a4.w};
    float pP[4] = {p4.x, p4.y, p4.z, p4.w};
    float outv[12];
    outv[0] = co[n];
    outv[1] = lt[n];
    #pragma unroll
    for (int i = 0; i < 4; i++) {
        float campU = big ? s_mA[c * 4 + i] : aP[i];
        // combined = 0.5*local + 0.3*(0.7*regional_sum) + 0.2*cluster
        float ampO = 0.7f * aP[i] + 0.3f * (0.5f * la[i] + 0.21f * ra[i] + 0.2f * campU);
        float cphU = big ? s_cPh[c * 4 + i] : pP[i];
        float phL = atan2f(ls[i], lc[i]);
        float phR = atan2f(rs[i], rc[i]);
        float phO = 0.7f * pP[i] + 0.3f * (0.5f * phL + 0.3f * phR + 0.2f * cphU);
        float s, cc;
        __sincosf(phO, &s, &cc);
        outv[2 + i] = ampO * cc;  // coeff of sin(w t)
        outv[6 + i] = ampO * s;   // coeff of cos(w t)
    }
    outv[10] = 0.f; outv[11] = 0.f;
    float4* dst = (float4*)(g_coefs + n * 12);
    dst[0] = make_float4(outv[0], outv[1], outv[2], outv[3]);
    dst[1] = make_float4(outv[4], outv[5], outv[6], outv[7]);
    dst[2] = make_float4(outv[8], outv[9], outv[10], outv[11]);
}

// ---------------------------------------------------------------------------
// Stage 3: 200MB fill with balanced slabs. Grid = 592 = 148 SMs x 4 blocks,
// one wave, each block covers a contiguous 84/85-node slab (1% imbalance vs
// the 32%-occupied second wave of the old 782-block grid).
// out[n,t] = c0 + lt*t + sum_i a_i*sin(w_i t) + b_i*cos(w_i t), f32x2 packed.
// ---------------------------------------------------------------------------
__global__ __launch_bounds__(256, 4) void k_fill(const float* __restrict__ tv,
                                                 float* __restrict__ out) {
    __shared__ ulonglong2 s_cp[MAXSLAB * 5];
    int start = (int)(((long long)blockIdx.x * NN) / GRIDF);
    int end   = (int)(((long long)(blockIdx.x + 1) * NN) / GRIDF);
    int nn = end - start;
    {
        ull* s_raw = (ull*)s_cp;
        for (int i = threadIdx.x; i < nn * 10; i += 256) {
            int node = i / 10, s = i - node * 10;
            float v = g_coefs[(start + node) * 12 + s];
            s_raw[node * 10 + s] = pk2(v, v);
        }
    }
    __syncthreads();

    int t0 = threadIdx.x * 4;
    if (t0 >= TT) return;  // threads 250..255 only helped staging

    float4 tvv = ((const float4*)tv)[threadIdx.x];
    ull T01 = pk2(tvv.x, tvv.y);
    ull T23 = pk2(tvv.z, tvv.w);

    const float w[4] = {TWOPI * 4.f, TWOPI * 2.f, TWOPI, TWOPI * 0.5f};
    ull S01[4], C01[4], S23[4], C23[4];
    #pragma unroll
    for (int i = 0; i < 4; i++) {
        float s0, c0, s1, c1, s2, c2, s3, c3;
        sincosf(w[i] * tvv.x, &s0, &c0);
        sincosf(w[i] * tvv.y, &s1, &c1);
        sincosf(w[i] * tvv.z, &s2, &c2);
        sincosf(w[i] * tvv.w, &s3, &c3);
        S01[i] = pk2(s0, s1); C01[i] = pk2(c0, c1);
        S23[i] = pk2(s2, s3); C23[i] = pk2(c2, c3);
    }

    #pragma unroll 2
    for (int j = 0; j < nn; j++) {
        ulonglong2 e0 = s_cp[j * 5 + 0];
        ulonglong2 e1 = s_cp[j * 5 + 1];
        ulonglong2 e2 = s_cp[j * 5 + 2];
        ulonglong2 e3 = s_cp[j * 5 + 3];
        ulonglong2 e4 = s_cp[j * 5 + 4];
        ull r0 = ffma2(e0.y, T01, e0.x);
        r0 = ffma2(e1.x, S01[0], r0); r0 = ffma2(e1.y, S01[1], r0);
        r0 = ffma2(e2.x, S01[2], r0); r0 = ffma2(e2.y, S01[3], r0);
        r0 = ffma2(e3.x, C01[0], r0); r0 = ffma2(e3.y, C01[1], r0);
        r0 = ffma2(e4.x, C01[2], r0); r0 = ffma2(e4.y, C01[3], r0);
        ull r1 = ffma2(e0.y, T23, e0.x);
        r1 = ffma2(e1.x, S23[0], r1); r1 = ffma2(e1.y, S23[1], r1);
        r1 = ffma2(e2.x, S23[2], r1); r1 = ffma2(e2.y, S23[3], r1);
        r1 = ffma2(e3.x, C23[0], r1); r1 = ffma2(e3.y, C23[1], r1);
        r1 = ffma2(e4.x, C23[2], r1); r1 = ffma2(e4.y, C23[3], r1);
        ulonglong2 o; o.x = r0; o.y = r1;
        *reinterpret_cast<ulonglong2*>(out + (size_t)(start + j) * TT + t0) = o;
    }
}

extern "C" void kernel_launch(void* const* d_in, const int* in_sizes, int n_in,
                              void* d_out, int out_size) {
    const float* tv  = (const float*)d_in[0];  // time_vector        [1000]
    const float* co  = (const float*)d_in[1];  // constant_offset    [50000]
    const float* lt  = (const float*)d_in[2];  // linear_trend       [50000]
    const float* amp = (const float*)d_in[3];  // seasonal_amplitudes[50000,4]
    const float* ph  = (const float*)d_in[4];  // seasonal_phases    [50000,4]
    const float* lw  = (const float*)d_in[5];  // local_w            [50000,5]
    const float* rw  = (const float*)d_in[6];  // regional_w         [50000,15]
    const int*   li  = (const int*)d_in[7];    // local_idx          [50000,5]
    const int*   ri  = (const int*)d_in[8];    // regional_idx       [50000,15]
    const int*   lab = (const int*)d_in[9];    // cluster_labels     [50000]
    float* out = (float*)d_out;

    k_pre<<<PREBLK, PRETHR>>>((const float4*)amp, (const float4*)ph, lab);
    k_coef<<<(NN + 255) / 256, 256>>>(amp, ph, lw, rw, li, ri, lab, co, lt);
    k_fill<<<GRIDF, 256>>>(tv, out);
}